// round 1
// baseline (speedup 1.0000x reference)
#include <cuda_runtime.h>

#define B_  1024
#define I_  256
#define N_  512
#define D_  6
#define U_  16
#define L_  64
#define ND_ (N_ * D_)   // 3072

// Scratch (static device allocation is allowed)
__device__ float g_W [I_ * ND_];   // sparsemax(feature_selection_logits), [I][N*D]
__device__ float g_FV[B_ * ND_];   // feature values, [B][N*D]
__device__ float g_sc[ND_];        // 0.5*exp(-lt)
__device__ float g_of[ND_];        // 0.5 - th*0.5*exp(-lt)

// ---------------------------------------------------------------------------
// Kernel A: sparsemax over last axis (D=6) for each (i, n)
// ---------------------------------------------------------------------------
__global__ void k_sparsemax(const float* __restrict__ fsl) {
    int idx = blockIdx.x * blockDim.x + threadIdx.x;
    if (idx >= I_ * N_) return;
    const float* z = fsl + (size_t)idx * D_;
    float z0 = z[0], z1 = z[1], z2 = z[2], z3 = z[3], z4 = z[4], z5 = z[5];
    float s0 = z0, s1 = z1, s2 = z2, s3 = z3, s4 = z4, s5 = z5;

    // Bose-Nelson 6-element sorting network, descending
#define CSWP(a, b) { float _mx = fmaxf(a, b); float _mn = fminf(a, b); a = _mx; b = _mn; }
    CSWP(s1, s2) CSWP(s4, s5) CSWP(s0, s2) CSWP(s3, s5)
    CSWP(s0, s1) CSWP(s3, s4) CSWP(s2, s5) CSWP(s0, s3)
    CSWP(s1, s4) CSWP(s2, s4) CSWP(s1, s3) CSWP(s2, s3)
#undef CSWP

    float cs = s0; int k = 1; float ts = cs;   // 1 + 1*s0 > s0 always holds
    cs += s1; if (1.0f + 2.0f * s1 > cs) { k = 2; ts = cs; }
    cs += s2; if (1.0f + 3.0f * s2 > cs) { k = 3; ts = cs; }
    cs += s3; if (1.0f + 4.0f * s3 > cs) { k = 4; ts = cs; }
    cs += s4; if (1.0f + 5.0f * s4 > cs) { k = 5; ts = cs; }
    cs += s5; if (1.0f + 6.0f * s5 > cs) { k = 6; ts = cs; }
    float tau = (ts - 1.0f) / (float)k;

    float* w = g_W + (size_t)idx * D_;
    w[0] = fmaxf(z0 - tau, 0.0f);
    w[1] = fmaxf(z1 - tau, 0.0f);
    w[2] = fmaxf(z2 - tau, 0.0f);
    w[3] = fmaxf(z3 - tau, 0.0f);
    w[4] = fmaxf(z4 - tau, 0.0f);
    w[5] = fmaxf(z5 - tau, 0.0f);
}

// ---------------------------------------------------------------------------
// Kernel SO: precompute scale/offset for the sparsemoid
// ---------------------------------------------------------------------------
__global__ void k_scaleoff(const float* __restrict__ th, const float* __restrict__ lt) {
    int idx = blockIdx.x * blockDim.x + threadIdx.x;
    if (idx >= ND_) return;
    float s = 0.5f * expf(-lt[idx]);
    g_sc[idx] = s;
    g_of[idx] = 0.5f - th[idx] * s;
}

// ---------------------------------------------------------------------------
// Kernel B: FV[b][nd] = sum_k x[b][k] * W[k][nd]
// M=1024, N=3072, K=256. 64x64 tile, 256 threads, 4x4 per thread.
// ---------------------------------------------------------------------------
__global__ void k_gemm(const float* __restrict__ x) {
    __shared__ float As[16][64];
    __shared__ float Bs[16][64];
    int t  = threadIdx.x;
    int tx = t & 15, ty = t >> 4;
    int row0 = blockIdx.y * 64, col0 = blockIdx.x * 64;

    float acc[4][4] = {};
    for (int kt = 0; kt < I_; kt += 16) {
        {   // A tile: [k][m]
            int m = t >> 2, kq = (t & 3) << 2;
            float4 v = *(const float4*)(x + (size_t)(row0 + m) * I_ + kt + kq);
            As[kq + 0][m] = v.x; As[kq + 1][m] = v.y;
            As[kq + 2][m] = v.z; As[kq + 3][m] = v.w;
        }
        {   // B tile: [k][j]
            int k = t >> 4, j = (t & 15) << 2;
            float4 v = *(const float4*)(g_W + (size_t)(kt + k) * ND_ + col0 + j);
            *(float4*)&Bs[k][j] = v;
        }
        __syncthreads();
#pragma unroll
        for (int kk = 0; kk < 16; kk++) {
            float4 a = *(float4*)&As[kk][ty << 2];
            float4 b = *(float4*)&Bs[kk][tx << 2];
            acc[0][0] += a.x * b.x; acc[0][1] += a.x * b.y; acc[0][2] += a.x * b.z; acc[0][3] += a.x * b.w;
            acc[1][0] += a.y * b.x; acc[1][1] += a.y * b.y; acc[1][2] += a.y * b.z; acc[1][3] += a.y * b.w;
            acc[2][0] += a.z * b.x; acc[2][1] += a.z * b.y; acc[2][2] += a.z * b.z; acc[2][3] += a.z * b.w;
            acc[3][0] += a.w * b.x; acc[3][1] += a.w * b.y; acc[3][2] += a.w * b.z; acc[3][3] += a.w * b.w;
        }
        __syncthreads();
    }
#pragma unroll
    for (int i = 0; i < 4; i++) {
        float4 v = make_float4(acc[i][0], acc[i][1], acc[i][2], acc[i][3]);
        *(float4*)(g_FV + (size_t)(row0 + (ty << 2) + i) * ND_ + col0 + (tx << 2)) = v;
    }
}

// ---------------------------------------------------------------------------
// Kernel C: bins -> leaf weights (prefix doubling) -> response contraction
// Block: 64 b's x 32 n's, 256 threads. acc over n in registers, atomics at end.
// ---------------------------------------------------------------------------
__global__ void k_forest(const float* __restrict__ resp, float* __restrict__ out) {
    __shared__ float resp_s[U_][68];   // [u][c], padded
    __shared__ float w_s[64][68];      // [b_local][c], padded
    __shared__ float sc_s[32 * 6];
    __shared__ float of_s[32 * 6];

    int t  = threadIdx.x;
    int bg = blockIdx.x;   // 16 b-groups of 64
    int ng = blockIdx.y;   // 16 n-chunks of 32

    if (t < 192) { sc_s[t] = g_sc[ng * 192 + t]; of_s[t] = g_of[ng * 192 + t]; }

    int bi = t & 31;       // FMA phase: b pair (bi, bi+32)
    int ui = t >> 5;       // FMA phase: u pair (ui, ui+8)
    int bw = t >> 2;       // w phase: local b
    int q  = t & 3;        // w phase: leaf quarter (bits 4,5)

    float acc00 = 0.0f, acc01 = 0.0f, acc10 = 0.0f, acc11 = 0.0f;

    for (int nl = 0; nl < 32; nl++) {
        int n = ng * 32 + nl;
        __syncthreads();   // protect smem from previous iteration's readers

        {   // stage response[n] : 1024 floats
            float4 rv = *(const float4*)(resp + (size_t)n * (U_ * L_) + t * 4);
            int u = t >> 4; int c = (t & 15) << 2;
            *(float4*)&resp_s[u][c] = rv;
        }
        {   // compute leaf weights for (bw, leaves q*16 .. q*16+15)
            const float* fvp = g_FV + (size_t)(bg * 64 + bw) * ND_ + n * D_;
            float h[6];
#pragma unroll
            for (int d = 0; d < 6; d++) {
                float hv = fvp[d] * sc_s[nl * 6 + d] + of_s[nl * 6 + d];
                h[d] = fminf(fmaxf(hv, 0.0f), 1.0f);
            }
            float f4 = (q & 1) ? (1.0f - h[4]) : h[4];
            float f5 = (q & 2) ? (1.0f - h[5]) : h[5];
            float pref = f4 * f5;
            float l1_0 = pref * h[0], l1_1 = pref * (1.0f - h[0]);
            float l2[4];
            l2[0] = l1_0 * h[1];          l2[1] = l1_1 * h[1];
            l2[2] = l1_0 * (1.0f - h[1]); l2[3] = l1_1 * (1.0f - h[1]);
            float l3[8];
#pragma unroll
            for (int j = 0; j < 4; j++) { l3[j] = l2[j] * h[2]; l3[4 + j] = l2[j] * (1.0f - h[2]); }
            float l4[16];
#pragma unroll
            for (int j = 0; j < 8; j++) { l4[j] = l3[j] * h[3]; l4[8 + j] = l3[j] * (1.0f - h[3]); }
#pragma unroll
            for (int j = 0; j < 16; j += 4)
                *(float4*)&w_s[bw][(q << 4) + j] = make_float4(l4[j], l4[j + 1], l4[j + 2], l4[j + 3]);
        }
        __syncthreads();

        // contraction: acc[bp][up] += sum_c w[b][c] * resp[u][c]
#pragma unroll
        for (int c = 0; c < 64; c += 4) {
            float4 wa = *(float4*)&w_s[bi][c];
            float4 wb = *(float4*)&w_s[bi + 32][c];
            float4 ra = *(float4*)&resp_s[ui][c];
            float4 rb = *(float4*)&resp_s[ui + 8][c];
            acc00 += wa.x * ra.x + wa.y * ra.y + wa.z * ra.z + wa.w * ra.w;
            acc01 += wa.x * rb.x + wa.y * rb.y + wa.z * rb.z + wa.w * rb.w;
            acc10 += wb.x * ra.x + wb.y * ra.y + wb.z * ra.z + wb.w * ra.w;
            acc11 += wb.x * rb.x + wb.y * rb.y + wb.z * rb.z + wb.w * rb.w;
        }
    }

    int b0 = bg * 64 + bi;
    int b1 = b0 + 32;
    atomicAdd(&out[b0 * U_ + ui],     acc00);
    atomicAdd(&out[b0 * U_ + ui + 8], acc01);
    atomicAdd(&out[b1 * U_ + ui],     acc10);
    atomicAdd(&out[b1 * U_ + ui + 8], acc11);
}

// ---------------------------------------------------------------------------
extern "C" void kernel_launch(void* const* d_in, const int* in_sizes, int n_in,
                              void* d_out, int out_size) {
    const float* x    = (const float*)d_in[0];  // [B, I]
    const float* fsl  = (const float*)d_in[1];  // [I, N, D]
    const float* th   = (const float*)d_in[2];  // [N, D]
    const float* lt   = (const float*)d_in[3];  // [N, D]
    const float* resp = (const float*)d_in[4];  // [N, U, 2^D]
    float* out = (float*)d_out;                 // [B, U]

    cudaMemsetAsync(out, 0, (size_t)B_ * U_ * sizeof(float), 0);

    k_sparsemax<<<(I_ * N_ + 255) / 256, 256>>>(fsl);
    k_scaleoff<<<(ND_ + 255) / 256, 256>>>(th, lt);
    k_gemm<<<dim3(ND_ / 64, B_ / 64), 256>>>(x);
    k_forest<<<dim3(B_ / 64, N_ / 32), 256>>>(resp, out);
}

// round 2
// speedup vs baseline: 1.4681x; 1.4681x over previous
#include <cuda_runtime.h>

#define B_  1024
#define I_  256
#define N_  512
#define D_  6
#define U_  16
#define L_  64
#define ND_ (N_ * D_)   // 3072

// Scratch (static device allocation is allowed)
__device__ float g_W  [I_ * ND_];   // sparsemax(feature_selection_logits), [I][ND]
__device__ float g_FVt[ND_ * B_];   // feature values TRANSPOSED, [ND][B]
__device__ float g_sc [ND_];        // 0.5*exp(-lt)
__device__ float g_of [ND_];        // 0.5 - th*0.5*exp(-lt)

typedef unsigned long long u64;

__device__ __forceinline__ void fma2(u64 &acc, u64 a, u64 b) {
    asm("fma.rn.f32x2 %0, %1, %2, %0;" : "+l"(acc) : "l"(a), "l"(b));
}
__device__ __forceinline__ u64 pack2(float lo, float hi) {
    u64 r; asm("mov.b64 %0, {%1, %2};" : "=l"(r) : "f"(lo), "f"(hi)); return r;
}
__device__ __forceinline__ void unpack2(float &lo, float &hi, u64 v) {
    asm("mov.b64 {%0, %1}, %2;" : "=f"(lo), "=f"(hi) : "l"(v));
}
__device__ __forceinline__ u64 d2l(double d) { return __double_as_longlong(d); }

// ---------------------------------------------------------------------------
// Kernel A: sparsemax over last axis (D=6) for each (i, n)
// ---------------------------------------------------------------------------
__global__ void k_sparsemax(const float* __restrict__ fsl) {
    int idx = blockIdx.x * blockDim.x + threadIdx.x;
    if (idx >= I_ * N_) return;
    const float* z = fsl + (size_t)idx * D_;
    float z0 = z[0], z1 = z[1], z2 = z[2], z3 = z[3], z4 = z[4], z5 = z[5];
    float s0 = z0, s1 = z1, s2 = z2, s3 = z3, s4 = z4, s5 = z5;

#define CSWP(a, b) { float _mx = fmaxf(a, b); float _mn = fminf(a, b); a = _mx; b = _mn; }
    CSWP(s1, s2) CSWP(s4, s5) CSWP(s0, s2) CSWP(s3, s5)
    CSWP(s0, s1) CSWP(s3, s4) CSWP(s2, s5) CSWP(s0, s3)
    CSWP(s1, s4) CSWP(s2, s4) CSWP(s1, s3) CSWP(s2, s3)
#undef CSWP

    float cs = s0; int k = 1; float ts = cs;
    cs += s1; if (1.0f + 2.0f * s1 > cs) { k = 2; ts = cs; }
    cs += s2; if (1.0f + 3.0f * s2 > cs) { k = 3; ts = cs; }
    cs += s3; if (1.0f + 4.0f * s3 > cs) { k = 4; ts = cs; }
    cs += s4; if (1.0f + 5.0f * s4 > cs) { k = 5; ts = cs; }
    cs += s5; if (1.0f + 6.0f * s5 > cs) { k = 6; ts = cs; }
    float tau = (ts - 1.0f) / (float)k;

    float* w = g_W + (size_t)idx * D_;
    w[0] = fmaxf(z0 - tau, 0.0f);
    w[1] = fmaxf(z1 - tau, 0.0f);
    w[2] = fmaxf(z2 - tau, 0.0f);
    w[3] = fmaxf(z3 - tau, 0.0f);
    w[4] = fmaxf(z4 - tau, 0.0f);
    w[5] = fmaxf(z5 - tau, 0.0f);
}

__global__ void k_scaleoff(const float* __restrict__ th, const float* __restrict__ lt) {
    int idx = blockIdx.x * blockDim.x + threadIdx.x;
    if (idx >= ND_) return;
    float s = 0.5f * expf(-lt[idx]);
    g_sc[idx] = s;
    g_of[idx] = 0.5f - th[idx] * s;
}

// ---------------------------------------------------------------------------
// Kernel B: FVt[m=nd][j=b] = sum_k W[k][m] * x[j][k]
// M=3072 (nd), Ncols=1024 (b), K=256. Tile 128m x 64j, 256 thr, 8x4/thread.
// f32x2 packed over m-pairs.
// ---------------------------------------------------------------------------
__global__ void k_gemm(const float* __restrict__ x) {
    __shared__ float As[16][128];   // [k][m]
    __shared__ float Bs[16][68];    // [k][j], padded

    int t  = threadIdx.x;
    int tx = t & 15;        // j quad: cols tx*4..tx*4+3
    int ty = t >> 4;        // m oct : rows ty*8..ty*8+7
    int j0 = blockIdx.x * 64;
    int m0 = blockIdx.y * 128;

    u64 acc2[4][4];
#pragma unroll
    for (int i = 0; i < 4; i++)
#pragma unroll
        for (int j = 0; j < 4; j++) acc2[i][j] = 0ull;

    for (int kt = 0; kt < I_; kt += 16) {
        {   // A tile: 2048 floats, 2 float4/thread, direct copy of W rows
            int k = t >> 4, mc = (t & 15) * 8;
            const float* src = g_W + (size_t)(kt + k) * ND_ + m0 + mc;
            *(float4*)&As[k][mc]     = *(const float4*)(src);
            *(float4*)&As[k][mc + 4] = *(const float4*)(src + 4);
        }
        {   // B tile: x transposed, [k][j]
            int j = t >> 2, kq = (t & 3) * 4;
            float4 v = *(const float4*)(x + (size_t)(j0 + j) * I_ + kt + kq);
            Bs[kq + 0][j] = v.x; Bs[kq + 1][j] = v.y;
            Bs[kq + 2][j] = v.z; Bs[kq + 3][j] = v.w;
        }
        __syncthreads();
#pragma unroll
        for (int kk = 0; kk < 16; kk++) {
            double2 a01 = *(const double2*)&As[kk][ty * 8];
            double2 a23 = *(const double2*)&As[kk][ty * 8 + 4];
            float4  bv  = *(const float4*)&Bs[kk][tx * 4];
            u64 am[4] = { d2l(a01.x), d2l(a01.y), d2l(a23.x), d2l(a23.y) };
            u64 bd[4] = { pack2(bv.x, bv.x), pack2(bv.y, bv.y),
                          pack2(bv.z, bv.z), pack2(bv.w, bv.w) };
#pragma unroll
            for (int mp = 0; mp < 4; mp++)
#pragma unroll
                for (int j = 0; j < 4; j++) fma2(acc2[mp][j], am[mp], bd[j]);
        }
        __syncthreads();
    }

#pragma unroll
    for (int mp = 0; mp < 4; mp++) {
        float lo0, hi0, lo1, hi1, lo2, hi2, lo3, hi3;
        unpack2(lo0, hi0, acc2[mp][0]);
        unpack2(lo1, hi1, acc2[mp][1]);
        unpack2(lo2, hi2, acc2[mp][2]);
        unpack2(lo3, hi3, acc2[mp][3]);
        int m = m0 + ty * 8 + mp * 2;
        *(float4*)(g_FVt + (size_t)m * B_ + j0 + tx * 4)       = make_float4(lo0, lo1, lo2, lo3);
        *(float4*)(g_FVt + (size_t)(m + 1) * B_ + j0 + tx * 4) = make_float4(hi0, hi1, hi2, hi3);
    }
}

// ---------------------------------------------------------------------------
// Kernel C: each thread owns one batch row b. Leaf weights in registers,
// resp broadcast from smem, f32x2 contraction, acc held across 16 n.
// Grid (B/256=4, N/16=32), 256 threads.
// ---------------------------------------------------------------------------
__global__ void k_forest(const float* __restrict__ resp, float* __restrict__ out) {
    __shared__ float resp_s[U_][L_];   // [u][c]
    __shared__ float sc_s[96], of_s[96];

    int t  = threadIdx.x;
    int bg = blockIdx.x;   // 4 groups of 256 b
    int ng = blockIdx.y;   // 32 chunks of 16 n
    int b  = bg * 256 + t;

    if (t < 96) { sc_s[t] = g_sc[ng * 96 + t]; of_s[t] = g_of[ng * 96 + t]; }
    __syncthreads();

    u64 acc2[U_];
#pragma unroll
    for (int u = 0; u < U_; u++) acc2[u] = 0ull;

    for (int nl = 0; nl < 16; nl++) {
        int n = ng * 16 + nl;

        // sparsemoid bins for this (b, n) — coalesced loads from FVt
        float h[6];
        const float* fvp = g_FVt + (size_t)n * 6 * B_ + b;
#pragma unroll
        for (int d = 0; d < 6; d++) {
            float hv = fvp[(size_t)d * B_] * sc_s[nl * 6 + d] + of_s[nl * 6 + d];
            h[d] = fminf(fmaxf(hv, 0.0f), 1.0f);
        }

        __syncthreads();   // previous iteration's resp_s readers done
        {   // stage response[n]: 1024 floats, 1 float4/thread
            int u = t >> 4, c4 = (t & 15) * 4;
            *(float4*)&resp_s[u][c4] = *(const float4*)(resp + (size_t)n * (U_ * L_) + t * 4);
        }
        __syncthreads();

        float g0 = 1.0f - h[0], g1 = 1.0f - h[1], g2 = 1.0f - h[2], g3 = 1.0f - h[3];
#pragma unroll
        for (int q = 0; q < 4; q++) {
            float f4 = (q & 1) ? (1.0f - h[4]) : h[4];
            float f5 = (q & 2) ? (1.0f - h[5]) : h[5];
            float pref = f4 * f5;
            float l1_0 = pref * h[0], l1_1 = pref * g0;
            float l2[4];
            l2[0] = l1_0 * h[1]; l2[1] = l1_1 * h[1];
            l2[2] = l1_0 * g1;   l2[3] = l1_1 * g1;
            float l3[8];
#pragma unroll
            for (int j = 0; j < 4; j++) { l3[j] = l2[j] * h[2]; l3[4 + j] = l2[j] * g2; }
            float l4[16];
#pragma unroll
            for (int j = 0; j < 8; j++) { l4[j] = l3[j] * h[3]; l4[8 + j] = l3[j] * g3; }

            u64 lp[8];
#pragma unroll
            for (int j = 0; j < 8; j++) lp[j] = pack2(l4[2 * j], l4[2 * j + 1]);

#pragma unroll
            for (int u = 0; u < U_; u++) {
                const double2* rp = (const double2*)&resp_s[u][q * 16];
#pragma unroll
                for (int j4 = 0; j4 < 4; j4++) {
                    double2 rv = rp[j4];                 // broadcast LDS.128
                    fma2(acc2[u], lp[2 * j4],     d2l(rv.x));
                    fma2(acc2[u], lp[2 * j4 + 1], d2l(rv.y));
                }
            }
        }
    }

#pragma unroll
    for (int u = 0; u < U_; u++) {
        float lo, hi; unpack2(lo, hi, acc2[u]);
        atomicAdd(&out[b * U_ + u], lo + hi);
    }
}

// ---------------------------------------------------------------------------
extern "C" void kernel_launch(void* const* d_in, const int* in_sizes, int n_in,
                              void* d_out, int out_size) {
    const float* x    = (const float*)d_in[0];  // [B, I]
    const float* fsl  = (const float*)d_in[1];  // [I, N, D]
    const float* th   = (const float*)d_in[2];  // [N, D]
    const float* lt   = (const float*)d_in[3];  // [N, D]
    const float* resp = (const float*)d_in[4];  // [N, U, 2^D]
    float* out = (float*)d_out;                 // [B, U]

    cudaMemsetAsync(out, 0, (size_t)B_ * U_ * sizeof(float), 0);

    k_sparsemax<<<(I_ * N_ + 255) / 256, 256>>>(fsl);
    k_scaleoff<<<(ND_ + 255) / 256, 256>>>(th, lt);
    k_gemm<<<dim3(B_ / 64, ND_ / 128), 256>>>(x);
    k_forest<<<dim3(B_ / 256, N_ / 16), 256>>>(resp, out);
}

// round 4
// speedup vs baseline: 1.5075x; 1.0268x over previous
#include <cuda_runtime.h>

#define B_  1024
#define I_  256
#define N_  512
#define D_  6
#define U_  16
#define L_  64
#define ND_ (N_ * D_)   // 3072

__device__ float g_W  [I_ * ND_];   // sparsemax(feature_selection_logits), [I][ND]
__device__ float g_FVt[ND_ * B_];   // feature values TRANSPOSED, [ND][B]
__device__ float g_sc [ND_];        // 0.5*exp(-lt)
__device__ float g_of [ND_];        // 0.5 - th*0.5*exp(-lt)

typedef unsigned long long u64;

__device__ __forceinline__ void fma2(u64 &acc, u64 a, u64 b) {
    asm("fma.rn.f32x2 %0, %1, %2, %0;" : "+l"(acc) : "l"(a), "l"(b));
}
__device__ __forceinline__ u64 pack2(float lo, float hi) {
    u64 r; asm("mov.b64 %0, {%1, %2};" : "=l"(r) : "f"(lo), "f"(hi)); return r;
}
__device__ __forceinline__ void unpack2(float &lo, float &hi, u64 v) {
    asm("mov.b64 {%0, %1}, %2;" : "=f"(lo), "=f"(hi) : "l"(v));
}
__device__ __forceinline__ u64 d2l(double d) { return __double_as_longlong(d); }

// ---------------------------------------------------------------------------
// Kernel A: sparsemax over last axis (D=6) for each (i, n)
// ---------------------------------------------------------------------------
__global__ void k_sparsemax(const float* __restrict__ fsl) {
    int idx = blockIdx.x * blockDim.x + threadIdx.x;
    if (idx >= I_ * N_) return;
    const float* z = fsl + (size_t)idx * D_;
    float z0 = z[0], z1 = z[1], z2 = z[2], z3 = z[3], z4 = z[4], z5 = z[5];
    float s0 = z0, s1 = z1, s2 = z2, s3 = z3, s4 = z4, s5 = z5;

#define CSWP(a, b) { float _mx = fmaxf(a, b); float _mn = fminf(a, b); a = _mx; b = _mn; }
    CSWP(s1, s2) CSWP(s4, s5) CSWP(s0, s2) CSWP(s3, s5)
    CSWP(s0, s1) CSWP(s3, s4) CSWP(s2, s5) CSWP(s0, s3)
    CSWP(s1, s4) CSWP(s2, s4) CSWP(s1, s3) CSWP(s2, s3)
#undef CSWP

    float cs = s0; int k = 1; float ts = cs;
    cs += s1; if (1.0f + 2.0f * s1 > cs) { k = 2; ts = cs; }
    cs += s2; if (1.0f + 3.0f * s2 > cs) { k = 3; ts = cs; }
    cs += s3; if (1.0f + 4.0f * s3 > cs) { k = 4; ts = cs; }
    cs += s4; if (1.0f + 5.0f * s4 > cs) { k = 5; ts = cs; }
    cs += s5; if (1.0f + 6.0f * s5 > cs) { k = 6; ts = cs; }
    float tau = (ts - 1.0f) / (float)k;

    float* w = g_W + (size_t)idx * D_;
    w[0] = fmaxf(z0 - tau, 0.0f);
    w[1] = fmaxf(z1 - tau, 0.0f);
    w[2] = fmaxf(z2 - tau, 0.0f);
    w[3] = fmaxf(z3 - tau, 0.0f);
    w[4] = fmaxf(z4 - tau, 0.0f);
    w[5] = fmaxf(z5 - tau, 0.0f);
}

__global__ void k_scaleoff(const float* __restrict__ th, const float* __restrict__ lt) {
    int idx = blockIdx.x * blockDim.x + threadIdx.x;
    if (idx >= ND_) return;
    float s = 0.5f * expf(-lt[idx]);
    g_sc[idx] = s;
    g_of[idx] = 0.5f - th[idx] * s;
}

// ---------------------------------------------------------------------------
// Kernel B: FVt[m=nd][j=b] = sum_k W[k][m] * x[j][k]
// M=3072 (nd), Ncols=1024 (b), K=256. Tile 128m x 64j, 256 thr, 8x4/thread.
// Register-prefetch double buffering over the 16 k-tiles.
// ---------------------------------------------------------------------------
__global__ void __launch_bounds__(256, 2) k_gemm(const float* __restrict__ x) {
    __shared__ float As[16][128];   // [k][m]
    __shared__ float Bs[16][68];    // [k][j], padded

    int t  = threadIdx.x;
    int tx = t & 15;        // j quad
    int ty = t >> 4;        // m oct
    int j0 = blockIdx.x * 64;
    int m0 = blockIdx.y * 128;

    // load indices
    int ak = t >> 4, amc = (t & 15) * 8;
    int bj = t >> 2, bkq = (t & 3) * 4;
    const float* aBase = g_W + (size_t)ak * ND_ + m0 + amc;
    const float* bBase = x + (size_t)(j0 + bj) * I_ + bkq;

    u64 acc2[4][4];
#pragma unroll
    for (int i = 0; i < 4; i++)
#pragma unroll
        for (int j = 0; j < 4; j++) acc2[i][j] = 0ull;

    // prologue: tile 0
    float4 pa0 = *(const float4*)(aBase);
    float4 pa1 = *(const float4*)(aBase + 4);
    float4 pb  = *(const float4*)(bBase);

    for (int kt = 0; kt < I_; kt += 16) {
        // commit prefetched tile to smem
        *(float4*)&As[ak][amc]     = pa0;
        *(float4*)&As[ak][amc + 4] = pa1;
        Bs[bkq + 0][bj] = pb.x; Bs[bkq + 1][bj] = pb.y;
        Bs[bkq + 2][bj] = pb.z; Bs[bkq + 3][bj] = pb.w;
        __syncthreads();

        // prefetch next tile while computing
        if (kt + 16 < I_) {
            pa0 = *(const float4*)(aBase + (size_t)(kt + 16) * ND_);
            pa1 = *(const float4*)(aBase + (size_t)(kt + 16) * ND_ + 4);
            pb  = *(const float4*)(bBase + kt + 16);
        }

#pragma unroll
        for (int kk = 0; kk < 16; kk++) {
            double2 a01 = *(const double2*)&As[kk][ty * 8];
            double2 a23 = *(const double2*)&As[kk][ty * 8 + 4];
            float4  bv  = *(const float4*)&Bs[kk][tx * 4];
            u64 am[4] = { d2l(a01.x), d2l(a01.y), d2l(a23.x), d2l(a23.y) };
            u64 bd[4] = { pack2(bv.x, bv.x), pack2(bv.y, bv.y),
                          pack2(bv.z, bv.z), pack2(bv.w, bv.w) };
#pragma unroll
            for (int mp = 0; mp < 4; mp++)
#pragma unroll
                for (int j = 0; j < 4; j++) fma2(acc2[mp][j], am[mp], bd[j]);
        }
        __syncthreads();
    }

#pragma unroll
    for (int mp = 0; mp < 4; mp++) {
        float lo0, hi0, lo1, hi1, lo2, hi2, lo3, hi3;
        unpack2(lo0, hi0, acc2[mp][0]);
        unpack2(lo1, hi1, acc2[mp][1]);
        unpack2(lo2, hi2, acc2[mp][2]);
        unpack2(lo3, hi3, acc2[mp][3]);
        int m = m0 + ty * 8 + mp * 2;
        *(float4*)(g_FVt + (size_t)m * B_ + j0 + tx * 4)       = make_float4(lo0, lo1, lo2, lo3);
        *(float4*)(g_FVt + (size_t)(m + 1) * B_ + j0 + tx * 4) = make_float4(hi0, hi1, hi2, hi3);
    }
}

// ---------------------------------------------------------------------------
// Kernel C: one thread = one batch row b. 128 threads/block, 8 n per block.
// Grid (8 b-groups, 64 n-chunks) = 512 blocks for full-chip occupancy.
// ---------------------------------------------------------------------------
__global__ void __launch_bounds__(128, 5) k_forest(const float* __restrict__ resp,
                                                   float* __restrict__ out) {
    __shared__ float resp_s[U_][L_];   // [u][c]
    __shared__ float sc_s[48], of_s[48];

    int t  = threadIdx.x;
    int bg = blockIdx.x;   // 8 groups of 128 b
    int ng = blockIdx.y;   // 64 chunks of 8 n
    int b  = bg * 128 + t;

    if (t < 48) { sc_s[t] = g_sc[ng * 48 + t]; of_s[t] = g_of[ng * 48 + t]; }
    __syncthreads();       // sc_s/of_s visible to ALL threads before first use

    u64 acc2[U_];
#pragma unroll
    for (int u = 0; u < U_; u++) acc2[u] = 0ull;

    for (int nl = 0; nl < 8; nl++) {
        int n = ng * 8 + nl;

        // sparsemoid bins for (b, n) — coalesced loads from FVt
        float h[6];
        const float* fvp = g_FVt + (size_t)n * 6 * B_ + b;
#pragma unroll
        for (int d = 0; d < 6; d++) {
            float hv = fvp[(size_t)d * B_] * sc_s[nl * 6 + d] + of_s[nl * 6 + d];
            h[d] = fminf(fmaxf(hv, 0.0f), 1.0f);
        }

        __syncthreads();   // previous iteration's resp_s readers done
        {   // stage response[n]: 1024 floats, 2 float4/thread
            const float4* src = (const float4*)(resp + (size_t)n * (U_ * L_));
            float4* dst = (float4*)&resp_s[0][0];
            dst[t]       = src[t];
            dst[t + 128] = src[t + 128];
        }
        __syncthreads();

        float g0 = 1.0f - h[0], g1 = 1.0f - h[1], g2 = 1.0f - h[2], g3 = 1.0f - h[3];
#pragma unroll
        for (int q = 0; q < 4; q++) {
            float f4 = (q & 1) ? (1.0f - h[4]) : h[4];
            float f5 = (q & 2) ? (1.0f - h[5]) : h[5];
            float pref = f4 * f5;
            float l1_0 = pref * h[0], l1_1 = pref * g0;
            float l2[4];
            l2[0] = l1_0 * h[1]; l2[1] = l1_1 * h[1];
            l2[2] = l1_0 * g1;   l2[3] = l1_1 * g1;
            float l3[8];
#pragma unroll
            for (int j = 0; j < 4; j++) { l3[j] = l2[j] * h[2]; l3[4 + j] = l2[j] * g2; }
            float l4[16];
#pragma unroll
            for (int j = 0; j < 8; j++) { l4[j] = l3[j] * h[3]; l4[8 + j] = l3[j] * g3; }

            u64 lp[8];
#pragma unroll
            for (int j = 0; j < 8; j++) lp[j] = pack2(l4[2 * j], l4[2 * j + 1]);

#pragma unroll
            for (int u = 0; u < U_; u++) {
                const double2* rp = (const double2*)&resp_s[u][q * 16];
#pragma unroll
                for (int j4 = 0; j4 < 4; j4++) {
                    double2 rv = rp[j4];                 // broadcast LDS.128
                    fma2(acc2[u], lp[2 * j4],     d2l(rv.x));
                    fma2(acc2[u], lp[2 * j4 + 1], d2l(rv.y));
                }
            }
        }
    }

#pragma unroll
    for (int u = 0; u < U_; u++) {
        float lo, hi; unpack2(lo, hi, acc2[u]);
        atomicAdd(&out[b * U_ + u], lo + hi);
    }
}

// ---------------------------------------------------------------------------
extern "C" void kernel_launch(void* const* d_in, const int* in_sizes, int n_in,
                              void* d_out, int out_size) {
    const float* x    = (const float*)d_in[0];  // [B, I]
    const float* fsl  = (const float*)d_in[1];  // [I, N, D]
    const float* th   = (const float*)d_in[2];  // [N, D]
    const float* lt   = (const float*)d_in[3];  // [N, D]
    const float* resp = (const float*)d_in[4];  // [N, U, 2^D]
    float* out = (float*)d_out;                 // [B, U]

    cudaMemsetAsync(out, 0, (size_t)B_ * U_ * sizeof(float), 0);

    k_sparsemax<<<(I_ * N_ + 255) / 256, 256>>>(fsl);
    k_scaleoff<<<(ND_ + 255) / 256, 256>>>(th, lt);
    k_gemm<<<dim3(B_ / 64, ND_ / 128), 256>>>(x);
    k_forest<<<dim3(B_ / 128, N_ / 8), 128>>>(resp, out);
}